// round 9
// baseline (speedup 1.0000x reference)
#include <cuda_runtime.h>
#include <cstdint>

#define SEQ_LEN  120
#define BATCH    2048
#define INPUT    6
#define HID      64
#define GATES    256
#define LAYERS   4
#define TLEN     120
#define NB       16
#define NCTA     (BATCH / NB)   // 128
#define NTHR     256

#define CHUNK_ROWS 32                     // k rows per chunk
#define CHUNK_F4   (CHUNK_ROWS * HID)     // 2048 float4 = 32KB
#define CHUNK_BYTES (CHUNK_F4 * 16)
#define W0_BYTES   (4 * HID * 32)         // 4 k-pairs x 64 hh x 32B = 8KB
#define NSLOT      6
#define CPS        15
#define TOTALC     (240 * CPS)

typedef unsigned long long ull;

// ---- k-paired gate streams ---------------------------------------------------
// chunk layout: [j=0..15][hh=0..63][2 x float4]:
//   f4 slot0 = (wi_k0, wi_k1, wf_k0, wf_k1), slot1 = (wg_k0, wg_k1, wo_k0, wo_k1)
// chunk order per step: c0,c1 = Whh L0; c2 = W0 (4 j, k>=6 zero);
// l>=1 base 3+4(l-1): Whh l (2), Wih l (2)
__device__ float4 g_stream_e[CPS * CHUNK_F4];
__device__ float4 g_stream_d[CPS * CHUNK_F4];

__global__ void lstm36206574305735_pack(
    const float* __restrict__ eW0, const float* __restrict__ eWih,
    const float* __restrict__ eWhh, const float* __restrict__ dW0,
    const float* __restrict__ dWih, const float* __restrict__ dWhh)
{
    const int tot = 2 * CPS * CHUNK_F4;
    for (int idx = blockIdx.x * blockDim.x + threadIdx.x; idx < tot;
         idx += gridDim.x * blockDim.x) {
        int p  = idx / (CPS * CHUNK_F4);
        int r  = idx % (CPS * CHUNK_F4);
        int c  = r / CHUNK_F4;
        int q  = r % CHUNK_F4;
        int slot = q & 1;              // 0: (i,f) pairs, 1: (g,o) pairs
        int cell = q >> 1;
        int j  = cell / HID;
        int hh = cell % HID;
        const float* W0  = p ? dW0  : eW0;
        const float* Wih = p ? dWih : eWih;
        const float* Whh = p ? dWhh : eWhh;

        int g0 = slot ? 2 : 0;         // gate base (g-slot: g,o ; else i,f)
        float4 v = make_float4(0.f, 0.f, 0.f, 0.f);
        if (c == 2) {                  // W0, Kdim=INPUT, k-padded
            int k0 = 2 * j, k1 = 2 * j + 1;
            float a0 = (k0 < INPUT) ? W0[((g0 + 0) * HID + hh) * INPUT + k0] : 0.f;
            float a1 = (k1 < INPUT) ? W0[((g0 + 0) * HID + hh) * INPUT + k1] : 0.f;
            float b0 = (k0 < INPUT) ? W0[((g0 + 1) * HID + hh) * INPUT + k0] : 0.f;
            float b1 = (k1 < INPUT) ? W0[((g0 + 1) * HID + hh) * INPUT + k1] : 0.f;
            v = make_float4(a0, a1, b0, b1);
        } else {
            const float* W; int kb;
            if (c < 2) { W = Whh; kb = c * CHUNK_ROWS; }                 // Whh L0
            else {
                int l  = (c - 3) / 4 + 1;
                int cc = (c - 3) % 4;
                if (cc < 2) { W = Whh + (size_t)l * GATES * HID;        kb = cc * CHUNK_ROWS; }
                else        { W = Wih + (size_t)(l - 1) * GATES * HID;  kb = (cc - 2) * CHUNK_ROWS; }
            }
            int k0 = kb + 2 * j, k1 = k0 + 1;
            v.x = W[((g0 + 0) * HID + hh) * HID + k0];
            v.y = W[((g0 + 0) * HID + hh) * HID + k1];
            v.z = W[((g0 + 1) * HID + hh) * HID + k0];
            v.w = W[((g0 + 1) * HID + hh) * HID + k1];
        }
        (p ? g_stream_d : g_stream_e)[r] = v;
    }
}

// ---- helpers ----------------------------------------------------------------
__device__ __forceinline__ void ffma2(ull& d, ull a, ull b) {
    asm("fma.rn.f32x2 %0, %1, %2, %0;" : "+l"(d) : "l"(a), "l"(b));
}
__device__ __forceinline__ float2 unpk(ull v) {
    float2 r; asm("mov.b64 {%0, %1}, %2;" : "=f"(r.x), "=f"(r.y) : "l"(v)); return r;
}
__device__ __forceinline__ float fsig(float x) {
    return __fdividef(1.0f, 1.0f + __expf(-x));
}
__device__ __forceinline__ float ftanh_(float x) {
    return 2.0f * fsig(2.0f * x) - 1.0f;
}
__device__ __forceinline__ uint32_t smem_u32(const void* p) {
    uint32_t a;
    asm("{ .reg .u64 t; cvta.to.shared.u64 t, %1; cvt.u32.u64 %0, t; }"
        : "=r"(a) : "l"(p));
    return a;
}
__device__ __forceinline__ void wait_parity(uint32_t mb, uint32_t parity) {
    asm volatile(
        "{\n\t"
        ".reg .pred P;\n\t"
        "WLOOP_%=:\n\t"
        "mbarrier.try_wait.parity.acquire.cta.shared::cta.b64 P, [%0], %1, 0x989680;\n\t"
        "@P bra WDONE_%=;\n\t"
        "bra WLOOP_%=;\n\t"
        "WDONE_%=:\n\t"
        "}"
        :: "r"(mb), "r"(parity) : "memory");
}

// k-paired gemv: per j (=2 k) : 4 LDS.128 + 16 FFMA2, zero MOVs.
// acc[g*4+b] lanes hold (even-k, odd-k) partial sums.
// hs layout: [j][b=0..15][2]  (h_{2j}[b], h_{2j+1}[b])
template <int JN>
__device__ __forceinline__ void gemv_s2(const ulonglong2* __restrict__ wslot,
                                        const float* __restrict__ hs,
                                        int hh, int bg, ull acc[16])
{
#pragma unroll 4
    for (int j = 0; j < JN; j++) {
        ulonglong2 wA = wslot[(j * HID + hh) * 2 + 0];   // (i-pair, f-pair)
        ulonglong2 wB = wslot[(j * HID + hh) * 2 + 1];   // (g-pair, o-pair)
        ulonglong2 hA = *(const ulonglong2*)(hs + j * 32 + bg * 8);
        ulonglong2 hB = *(const ulonglong2*)(hs + j * 32 + bg * 8 + 4);
        ffma2(acc[0],  wA.x, hA.x); ffma2(acc[1],  wA.x, hA.y);
        ffma2(acc[2],  wA.x, hB.x); ffma2(acc[3],  wA.x, hB.y);
        ffma2(acc[4],  wA.y, hA.x); ffma2(acc[5],  wA.y, hA.y);
        ffma2(acc[6],  wA.y, hB.x); ffma2(acc[7],  wA.y, hB.y);
        ffma2(acc[8],  wB.x, hA.x); ffma2(acc[9],  wB.x, hA.y);
        ffma2(acc[10], wB.x, hB.x); ffma2(acc[11], wB.x, hB.y);
        ffma2(acc[12], wB.y, hA.x); ffma2(acc[13], wB.y, hA.y);
        ffma2(acc[14], wB.y, hB.x); ffma2(acc[15], wB.y, hB.y);
    }
}

// ---- smem layout ------------------------------------------------------------
#define RING_SZ   (NSLOT * CHUNK_BYTES)     // 196608
#define MBAR_B    RING_SZ
#define FB_B      (RING_SZ + 64)
#define HD_F      0                          // [4][32 j][16 b][2] k-interleaved h
#define SZ_HD     (LAYERS * HID * 16)        // 4096
#define IND_F     (HD_F + SZ_HD)             // [4 j][16 b][2], j=3 zero
#define SZ_IND    (4 * 32)
#define LW_F      (IND_F + SZ_IND)
#define LB_F      (LW_F + HID * INPUT)
#define BIAS_F    (LB_F + 8)                 // float4[2][4][64] = 2048 floats
#define SZ_BIAS   (2 * LAYERS * HID * 4)
#define SMEM_TOTAL_B (FB_B + (BIAS_F + SZ_BIAS) * 4)

__global__ void __launch_bounds__(NTHR, 1)
lstm36206574305735_main(const float* __restrict__ x,
                        const float* __restrict__ eB,
                        const float* __restrict__ dB,
                        const float* __restrict__ linW,
                        const float* __restrict__ linB,
                        float* __restrict__ out)
{
    extern __shared__ char sm[];
    const uint32_t ring_u = smem_u32(sm);
    const uint32_t mbar_u = ring_u + MBAR_B;
    float* fb   = (float*)(sm + FB_B);
    float* hd   = fb + HD_F;
    float* ind  = fb + IND_F;
    float* lw_s = fb + LW_F;
    float* lb_s = fb + LB_F;
    float4* bias = (float4*)(fb + BIAS_F);

    const int tid = threadIdx.x;
    const int hh  = tid >> 2;
    const int bg  = tid & 3;
    const int b0  = blockIdx.x * NB;

    if (tid == 0) {
        for (int s = 0; s < NSLOT; s++)
            asm volatile("mbarrier.init.shared.b64 [%0], 1;"
                         :: "r"(mbar_u + s * 8) : "memory");
        asm volatile("fence.proxy.async.shared::cta;" ::: "memory");
    }
    for (int i = tid; i < SZ_HD; i += NTHR) hd[i] = 0.0f;
    for (int i = tid; i < SZ_IND; i += NTHR) ind[i] = 0.0f;
    for (int i = tid; i < HID * INPUT; i += NTHR) {
        int h2 = i / INPUT, ii2 = i % INPUT;
        lw_s[h2 * INPUT + ii2] = linW[ii2 * HID + h2];
    }
    if (tid < INPUT) lb_s[tid] = linB[tid];
    for (int u = tid; u < 2 * LAYERS * HID; u += NTHR) {
        int phase = u >> 8, l = (u >> 6) & 3, hx = u & 63;
        const float* B = phase ? dB : eB;
        bias[u] = make_float4(B[l * GATES + hx],
                              B[l * GATES + HID + hx],
                              B[l * GATES + 2 * HID + hx],
                              B[l * GATES + 3 * HID + hx]);
    }
    __syncthreads();

    auto issue_one = [&](int G) {
        if (G >= TOTALC) return;
        int s = G % NSLOT;
        int cc = G % CPS;
        const float4* src = (G < 120 * CPS ? g_stream_e : g_stream_d)
                            + (size_t)cc * CHUNK_F4;
        uint32_t bytes = (cc == 2) ? (uint32_t)W0_BYTES : (uint32_t)CHUNK_BYTES;
        uint32_t mb = mbar_u + s * 8;
        asm volatile("mbarrier.arrive.expect_tx.shared.b64 _, [%0], %1;"
                     :: "r"(mb), "r"(bytes) : "memory");
        asm volatile("cp.async.bulk.shared::cluster.global.mbarrier::complete_tx::bytes "
                     "[%0], [%1], %2, [%3];"
                     :: "r"(ring_u + (uint32_t)s * CHUNK_BYTES), "l"(src),
                        "r"(bytes), "r"(mb) : "memory");
    };
    if (tid == 0)
        for (int g = 0; g < NSLOT; g++) issue_one(g);

    int Gi = NSLOT, cap = NSLOT;

    auto wait_chunk = [&](int G) -> const ulonglong2* {
        int s = G % NSLOT;
        wait_parity(mbar_u + s * 8, (unsigned)((G / NSLOT) & 1));
        return (const ulonglong2*)(sm + (size_t)s * CHUNK_BYTES);
    };
    auto barrier_issue = [&](int add) {
        __syncthreads();
        cap += add;
        if (tid == 0)
            for (; Gi < cap; Gi++) issue_one(Gi);
        else
            Gi = cap;
    };

    float c_reg[LAYERS][4];
#pragma unroll
    for (int l = 0; l < LAYERS; l++)
#pragma unroll
        for (int bi = 0; bi < 4; bi++) c_reg[l][bi] = 0.0f;

    const int  bb  = tid / INPUT;
    const int  ii  = tid % INPUT;
    const bool isx = tid < INPUT * NB;
    float xreg = 0.0f;
    if (isx) xreg = x[(size_t)(b0 + bb) * INPUT + ii];

    // layer: Whh gemv(old h[l]) -> BAR(+issue) -> Wih/W0 gemv -> cell epilogue
    auto do_layer = [&](int phase, int l, int cbase, int add, bool isL0) {
        ull acc[16];
#pragma unroll
        for (int i = 0; i < 16; i++) acc[i] = 0ull;

        const float* hl = hd + l * (HID * 16);
        { const ulonglong2* wp = wait_chunk(cbase);     gemv_s2<16>(wp, hl,       hh, bg, acc); }
        { const ulonglong2* wp = wait_chunk(cbase + 1); gemv_s2<16>(wp, hl + 512, hh, bg, acc); }

        barrier_issue(add);

        if (isL0) {
            const ulonglong2* wp = wait_chunk(cbase + 2);
            gemv_s2<4>(wp, ind, hh, bg, acc);
        } else {
            const float* hp = hd + (l - 1) * (HID * 16);
            { const ulonglong2* wp = wait_chunk(cbase + 2); gemv_s2<16>(wp, hp,       hh, bg, acc); }
            { const ulonglong2* wp = wait_chunk(cbase + 3); gemv_s2<16>(wp, hp + 512, hh, bg, acc); }
        }

        float4 bv = bias[(phase * LAYERS + l) * HID + hh];
        float* hbase = hd + l * (HID * 16) + (hh >> 1) * 32 + (hh & 1);
#pragma unroll
        for (int bi = 0; bi < 4; bi++) {
            float2 pi = unpk(acc[0 * 4 + bi]);
            float2 pf = unpk(acc[1 * 4 + bi]);
            float2 pg = unpk(acc[2 * 4 + bi]);
            float2 po = unpk(acc[3 * 4 + bi]);
            float gi_ = bv.x + pi.x + pi.y;
            float gf_ = bv.y + pf.x + pf.y;
            float gg_ = bv.z + pg.x + pg.y;
            float go_ = bv.w + po.x + po.y;
            float c = fmaf(fsig(gf_), c_reg[l][bi], fsig(gi_) * ftanh_(gg_));
            c_reg[l][bi] = c;
            float hv = fsig(go_) * ftanh_(c);
            hbase[(bg * 4 + bi) * 2] = hv;     // [j=hh>>1][b][par=hh&1]
        }
    };

    // -------- encoder --------
    int Gstep = 0;
    for (int t = 0; t < SEQ_LEN; t++) {
        if (isx) {
            ind[(ii >> 1) * 32 + bb * 2 + (ii & 1)] = xreg;
            if (t + 1 < SEQ_LEN)
                xreg = x[((size_t)(t + 1) * BATCH + b0 + bb) * INPUT + ii];
        }
        do_layer(0, 0, Gstep + 0,  t == 0 ? 2 : 4, true);
        do_layer(0, 1, Gstep + 3,  3, false);
        do_layer(0, 2, Gstep + 7,  4, false);
        do_layer(0, 3, Gstep + 11, 4, false);
        Gstep += CPS;
    }
    // ind still holds x[SEQ_LEN-1] — decoder seed

    // -------- decoder --------
    for (int t = 0; t < TLEN; t++) {
        do_layer(1, 0, Gstep + 0,  4, true);
        do_layer(1, 1, Gstep + 3,  3, false);
        do_layer(1, 2, Gstep + 7,  4, false);
        do_layer(1, 3, Gstep + 11, 4, false);
        Gstep += CPS;

        __syncthreads();   // h[3] visible to all warps
        if (isx) {
            const float* htop = hd + 3 * (HID * 16);
            float v = lb_s[ii];
#pragma unroll 8
            for (int h2 = 0; h2 < HID; h2++)
                v += lw_s[h2 * INPUT + ii] * htop[(h2 >> 1) * 32 + bb * 2 + (h2 & 1)];
            out[((size_t)t * BATCH + b0 + bb) * INPUT + ii] = v;
            ind[(ii >> 1) * 32 + bb * 2 + (ii & 1)] = v;
        }
    }
}

extern "C" void kernel_launch(void* const* d_in, const int* in_sizes, int n_in,
                              void* d_out, int out_size)
{
    const float* x    = (const float*)d_in[0];
    const float* eW0  = (const float*)d_in[1];
    const float* eWih = (const float*)d_in[2];
    const float* eWhh = (const float*)d_in[3];
    const float* eB   = (const float*)d_in[4];
    const float* dW0  = (const float*)d_in[5];
    const float* dWih = (const float*)d_in[6];
    const float* dWhh = (const float*)d_in[7];
    const float* dB   = (const float*)d_in[8];
    const float* linW = (const float*)d_in[9];
    const float* linB = (const float*)d_in[10];
    float* out = (float*)d_out;

    lstm36206574305735_pack<<<240, 256>>>(eW0, eWih, eWhh, dW0, dWih, dWhh);

    cudaFuncSetAttribute(lstm36206574305735_main,
                         cudaFuncAttributeMaxDynamicSharedMemorySize, SMEM_TOTAL_B);
    lstm36206574305735_main<<<NCTA, NTHR, SMEM_TOTAL_B>>>(x, eB, dB, linW, linB, out);
}

// round 10
// speedup vs baseline: 1.0175x; 1.0175x over previous
#include <cuda_runtime.h>
#include <cstdint>

#define SEQ_LEN  120
#define BATCH    2048
#define INPUT    6
#define HID      64
#define GATES    256
#define LAYERS   4
#define TLEN     120
#define NB       16
#define NCTA     (BATCH / NB)   // 128
#define NTHR     256

#define CHUNK_ROWS 32
#define CHUNK_F4   (CHUNK_ROWS * HID)     // 2048 float4 = 32KB
#define CHUNK_BYTES (CHUNK_F4 * 16)
#define NSLOT      5
#define CPS        14                     // streamed chunks per step (W0 resident)
#define TOTALC     (240 * CPS)            // 3360
#define RES_ROWS   8
#define RES_F4     (RES_ROWS * HID)       // 512
#define RES_BYTES  (RES_F4 * 16)          // 8192

typedef unsigned long long ull;

// stream chunk map per step: c0,c1=Whh L0; then per l>=1 base 2+4(l-1):
//   Whh l (2 chunks), Wih l (2 chunks)
__device__ float4 g_stream_e[CPS * CHUNK_F4];
__device__ float4 g_stream_d[CPS * CHUNK_F4];
__device__ float4 g_res_e[RES_F4];        // W0 k-padded to 8 rows
__device__ float4 g_res_d[RES_F4];

__global__ void lstm36206574305735_pack(
    const float* __restrict__ eW0, const float* __restrict__ eWih,
    const float* __restrict__ eWhh, const float* __restrict__ dW0,
    const float* __restrict__ dWih, const float* __restrict__ dWhh)
{
    const int PER = CPS * CHUNK_F4 + RES_F4;
    const int tot = 2 * PER;
    for (int idx = blockIdx.x * blockDim.x + threadIdx.x; idx < tot;
         idx += gridDim.x * blockDim.x) {
        int p = idx / PER;
        int r = idx % PER;
        const float* W0  = p ? dW0  : eW0;
        const float* Wih = p ? dWih : eWih;
        const float* Whh = p ? dWhh : eWhh;
        if (r < CPS * CHUNK_F4) {
            int c  = r / CHUNK_F4;
            int rr = r % CHUNK_F4;
            int kc = rr / HID;
            int hh = rr % HID;
            const float* W; int k;
            if (c < 2) { W = Whh; k = c * CHUNK_ROWS + kc; }
            else {
                int l = (c - 2) / 4 + 1;
                int q = (c - 2) % 4;
                if (q < 2) { W = Whh + (size_t)l * GATES * HID;       k = q * CHUNK_ROWS + kc; }
                else       { W = Wih + (size_t)(l - 1) * GATES * HID; k = (q - 2) * CHUNK_ROWS + kc; }
            }
            float4 v;
            v.x = W[(0 * HID + hh) * HID + k];
            v.y = W[(1 * HID + hh) * HID + k];
            v.z = W[(2 * HID + hh) * HID + k];
            v.w = W[(3 * HID + hh) * HID + k];
            (p ? g_stream_d : g_stream_e)[r] = v;
        } else {
            int q  = r - CPS * CHUNK_F4;
            int k  = q / HID;
            int hh = q % HID;
            float4 v = make_float4(0.f, 0.f, 0.f, 0.f);
            if (k < INPUT) {
                v.x = W0[(0 * HID + hh) * INPUT + k];
                v.y = W0[(1 * HID + hh) * INPUT + k];
                v.z = W0[(2 * HID + hh) * INPUT + k];
                v.w = W0[(3 * HID + hh) * INPUT + k];
            }
            (p ? g_res_d : g_res_e)[q] = v;
        }
    }
}

// ---- helpers ----------------------------------------------------------------
__device__ __forceinline__ void ffma2(ull& d, ull a, ull b) {
    asm("fma.rn.f32x2 %0, %1, %2, %0;" : "+l"(d) : "l"(a), "l"(b));
}
__device__ __forceinline__ ull dup2(float a) {
    ull v; asm("mov.b64 %0, {%1, %1};" : "=l"(v) : "f"(a)); return v;
}
__device__ __forceinline__ float2 unpk(ull v) {
    float2 r; asm("mov.b64 {%0, %1}, %2;" : "=f"(r.x), "=f"(r.y) : "l"(v)); return r;
}
__device__ __forceinline__ float fsig(float x) {
    return __fdividef(1.0f, 1.0f + __expf(-x));
}
__device__ __forceinline__ float ftanh_(float x) {
    return 2.0f * fsig(2.0f * x) - 1.0f;
}
__device__ __forceinline__ uint32_t smem_u32(const void* p) {
    uint32_t a;
    asm("{ .reg .u64 t; cvta.to.shared.u64 t, %1; cvt.u32.u64 %0, t; }"
        : "=r"(a) : "l"(p));
    return a;
}
__device__ __forceinline__ void wait_parity(uint32_t mb, uint32_t parity) {
    asm volatile(
        "{\n\t"
        ".reg .pred P;\n\t"
        "WLOOP_%=:\n\t"
        "mbarrier.try_wait.parity.acquire.cta.shared::cta.b64 P, [%0], %1, 0x989680;\n\t"
        "@P bra WDONE_%=;\n\t"
        "bra WLOOP_%=;\n\t"
        "WDONE_%=:\n\t"
        "}"
        :: "r"(mb), "r"(parity) : "memory");
}

// R5/R7 gemv: per k = 2 LDS.128 + 4 dup MOVs + 8 FFMA2
template <int K>
__device__ __forceinline__ void gemv_s(const float4* __restrict__ wslot,
                                       const float* __restrict__ hs,
                                       int hh, int bg, ull acc[8])
{
#pragma unroll 8
    for (int k = 0; k < K; k++) {
        float4 w4 = wslot[k * HID + hh];
        ulonglong2 hv = *(const ulonglong2*)(hs + k * 16 + bg * 4);
        ull wi = dup2(w4.x), wf = dup2(w4.y), wg = dup2(w4.z), wo = dup2(w4.w);
        ffma2(acc[0], wi, hv.x); ffma2(acc[1], wi, hv.y);
        ffma2(acc[2], wf, hv.x); ffma2(acc[3], wf, hv.y);
        ffma2(acc[4], wg, hv.x); ffma2(acc[5], wg, hv.y);
        ffma2(acc[6], wo, hv.x); ffma2(acc[7], wo, hv.y);
    }
}

// ---- smem layout ------------------------------------------------------------
#define RING_SZ   (NSLOT * CHUNK_BYTES)     // 163840
#define RES_OFF   RING_SZ                   // +8192
#define MBAR_B    (RES_OFF + RES_BYTES)     // 172032 (6 mbarriers: 5 ring + rmb)
#define FB_B      (MBAR_B + 64)
#define HD_F      0
#define SZ_HD     (LAYERS * HID * 16)       // 4096
#define IND_F     (HD_F + SZ_HD)            // [8][16], rows 6,7 zero
#define SZ_IND    (8 * 16)
#define LW_F      (IND_F + SZ_IND)
#define LB_F      (LW_F + HID * INPUT)
#define BIAS_F    (LB_F + 8)                // ull[2][4][64][4] = 4096 floats
#define SZ_BIAS   (2 * LAYERS * HID * 8)
#define SMEM_TOTAL_B (FB_B + (BIAS_F + SZ_BIAS) * 4)   // ~206.9KB

__global__ void __launch_bounds__(NTHR, 1)
lstm36206574305735_main(const float* __restrict__ x,
                        const float* __restrict__ eB,
                        const float* __restrict__ dB,
                        const float* __restrict__ linW,
                        const float* __restrict__ linB,
                        float* __restrict__ out)
{
    extern __shared__ char sm[];
    const uint32_t ring_u = smem_u32(sm);
    const uint32_t mbar_u = ring_u + MBAR_B;
    const uint32_t rmb_u  = mbar_u + NSLOT * 8;
    float* fb   = (float*)(sm + FB_B);
    float* hd   = fb + HD_F;
    float* ind  = fb + IND_F;
    float* lw_s = fb + LW_F;
    float* lb_s = fb + LB_F;
    ull*   bias = (ull*)(fb + BIAS_F);

    const int tid = threadIdx.x;
    const int hh  = tid >> 2;
    const int bg  = tid & 3;
    const int b0  = blockIdx.x * NB;

    auto issue_one = [&](int G) {
        if (G >= TOTALC) return;
        int s = G % NSLOT;
        int cc = G % CPS;
        const float4* src = (G < 120 * CPS ? g_stream_e : g_stream_d)
                            + (size_t)cc * CHUNK_F4;
        uint32_t mb = mbar_u + s * 8;
        asm volatile("mbarrier.arrive.expect_tx.shared.b64 _, [%0], %1;"
                     :: "r"(mb), "r"((uint32_t)CHUNK_BYTES) : "memory");
        asm volatile("cp.async.bulk.shared::cluster.global.mbarrier::complete_tx::bytes "
                     "[%0], [%1], %2, [%3];"
                     :: "r"(ring_u + (uint32_t)s * CHUNK_BYTES), "l"(src),
                        "r"((uint32_t)CHUNK_BYTES), "r"(mb) : "memory");
    };
    auto issue_res = [&](int p) {
        const float4* src = p ? g_res_d : g_res_e;
        asm volatile("mbarrier.arrive.expect_tx.shared.b64 _, [%0], %1;"
                     :: "r"(rmb_u), "r"((uint32_t)RES_BYTES) : "memory");
        asm volatile("cp.async.bulk.shared::cluster.global.mbarrier::complete_tx::bytes "
                     "[%0], [%1], %2, [%3];"
                     :: "r"(ring_u + (uint32_t)RES_OFF), "l"(src),
                        "r"((uint32_t)RES_BYTES), "r"(rmb_u) : "memory");
    };
    // leader-only wait for one chunk
    auto lw = [&](int G) {
        if (G >= TOTALC) return;
        wait_parity(mbar_u + (G % NSLOT) * 8, (uint32_t)((G / NSLOT) & 1));
    };

    if (tid == 0) {
        for (int s = 0; s < NSLOT + 1; s++)
            asm volatile("mbarrier.init.shared.b64 [%0], 1;"
                         :: "r"(mbar_u + s * 8) : "memory");
        asm volatile("fence.proxy.async.shared::cta;" ::: "memory");
        issue_res(0);
        for (int g = 0; g < NSLOT; g++) issue_one(g);
    }

    for (int i = tid; i < SZ_HD; i += NTHR) hd[i] = 0.0f;
    for (int i = tid; i < SZ_IND; i += NTHR) ind[i] = 0.0f;
    for (int i = tid; i < HID * INPUT; i += NTHR) {
        int h2 = i / INPUT, ii2 = i % INPUT;
        lw_s[h2 * INPUT + ii2] = linW[ii2 * HID + h2];
    }
    if (tid < INPUT) lb_s[tid] = linB[tid];
    for (int u = tid; u < 2 * LAYERS * HID; u += NTHR) {
        int phase = u >> 8, l = (u >> 6) & 3, hx = u & 63;
        const float* B = phase ? dB : eB;
        bias[u * 4 + 0] = dup2(B[l * GATES + hx]);
        bias[u * 4 + 1] = dup2(B[l * GATES + HID + hx]);
        bias[u * 4 + 2] = dup2(B[l * GATES + 2 * HID + hx]);
        bias[u * 4 + 3] = dup2(B[l * GATES + 3 * HID + hx]);
    }

    float c_reg[LAYERS][4];
#pragma unroll
    for (int l = 0; l < LAYERS; l++)
#pragma unroll
        for (int bi = 0; bi < 4; bi++) c_reg[l][bi] = 0.0f;

    const int  bb  = tid / INPUT;
    const int  ii  = tid % INPUT;
    const bool isx = tid < INPUT * NB;
    float xreg = 0.0f;
    if (isx) xreg = x[(size_t)(b0 + bb) * INPUT + ii];

    // leader waits resident + first two chunks, then everyone enters S0
    if (tid == 0) { wait_parity(rmb_u, 0); lw(0); lw(1); }
    __syncthreads();

    auto slotp = [&](int G) -> const float4* {
        return (const float4*)(sm + (size_t)(G % NSLOT) * CHUNK_BYTES);
    };
    auto initb = [&](int p, int l, ull acc[8]) {
        const ull* bv = bias + ((p * LAYERS + l) * HID + hh) * 4;
        acc[0] = acc[1] = bv[0];
        acc[2] = acc[3] = bv[1];
        acc[4] = acc[5] = bv[2];
        acc[6] = acc[7] = bv[3];
    };
    auto epi = [&](int l, ull acc[8]) {
        float2 ai0 = unpk(acc[0]), ai1 = unpk(acc[1]);
        float2 af0 = unpk(acc[2]), af1 = unpk(acc[3]);
        float2 ag0 = unpk(acc[4]), ag1 = unpk(acc[5]);
        float2 ao0 = unpk(acc[6]), ao1 = unpk(acc[7]);
        float ai[4] = {ai0.x, ai0.y, ai1.x, ai1.y};
        float af[4] = {af0.x, af0.y, af1.x, af1.y};
        float ag[4] = {ag0.x, ag0.y, ag1.x, ag1.y};
        float ao[4] = {ao0.x, ao0.y, ao1.x, ao1.y};
        float hout[4];
#pragma unroll
        for (int bi = 0; bi < 4; bi++) {
            float c = fmaf(fsig(af[bi]), c_reg[l][bi],
                           fsig(ai[bi]) * ftanh_(ag[bi]));
            c_reg[l][bi] = c;
            hout[bi] = fsig(ao[bi]) * ftanh_(c);
        }
        float* hrow = hd + (l * HID + hh) * 16 + bg * 4;
        *(float4*)hrow = make_float4(hout[0], hout[1], hout[2], hout[3]);
    };

    int G = 0;
    for (int t = 0; t < SEQ_LEN + TLEN; t++) {
        const bool dec = (t >= SEQ_LEN);
        const int  p   = dec ? 1 : 0;
        if (!dec && isx) {
            ind[ii * 16 + bb] = xreg;
            if (t + 1 < SEQ_LEN)
                xreg = x[((size_t)(t + 1) * BATCH + b0 + bb) * INPUT + ii];
        }

        ull acc[8];
        float* h0 = hd;
        float* h1 = hd + 1024;
        float* h2 = hd + 2048;
        float* h3 = hd + 3072;

        // S0: Whh L0 (c0,c1) over old h0
        initb(p, 0, acc);
        gemv_s<32>(slotp(G + 0), h0,       hh, bg, acc);
        gemv_s<32>(slotp(G + 1), h0 + 512, hh, bg, acc);
        __syncthreads();
        if (tid == 0) { issue_one(G + 5); issue_one(G + 6); }

        // S1: W0 (resident) + epi0
        gemv_s<8>((const float4*)(sm + RES_OFF), ind, hh, bg, acc);
        epi(0, acc);
        if (tid == 0) { lw(G + 2); lw(G + 3); }
        __syncthreads();
        if (tid == 0 && t == SEQ_LEN - 1) issue_res(1);

        // S2: Whh L1 (c2,c3) over old h1
        initb(p, 1, acc);
        gemv_s<32>(slotp(G + 2), h1,       hh, bg, acc);
        gemv_s<32>(slotp(G + 3), h1 + 512, hh, bg, acc);
        if (tid == 0) { lw(G + 4); lw(G + 5); }
        __syncthreads();
        if (tid == 0) { issue_one(G + 7); issue_one(G + 8); }

        // S3: Wih L1 (c4,c5) over new h0 + epi1
        gemv_s<32>(slotp(G + 4), h0,       hh, bg, acc);
        gemv_s<32>(slotp(G + 5), h0 + 512, hh, bg, acc);
        epi(1, acc);
        if (tid == 0) { lw(G + 6); lw(G + 7); }
        __syncthreads();
        if (tid == 0) { issue_one(G + 9); issue_one(G + 10); }

        // S4: Whh L2 (c6,c7) over old h2
        initb(p, 2, acc);
        gemv_s<32>(slotp(G + 6), h2,       hh, bg, acc);
        gemv_s<32>(slotp(G + 7), h2 + 512, hh, bg, acc);
        if (tid == 0) { lw(G + 8); lw(G + 9); }
        __syncthreads();
        if (tid == 0) { issue_one(G + 11); issue_one(G + 12); }

        // S5: Wih L2 (c8,c9) over new h1 + epi2
        gemv_s<32>(slotp(G + 8), h1,       hh, bg, acc);
        gemv_s<32>(slotp(G + 9), h1 + 512, hh, bg, acc);
        epi(2, acc);
        if (tid == 0) { lw(G + 10); lw(G + 11); }
        __syncthreads();
        if (tid == 0) { issue_one(G + 13); issue_one(G + 14); }

        // S6: Whh L3 (c10,c11) over old h3
        initb(p, 3, acc);
        gemv_s<32>(slotp(G + 10), h3,       hh, bg, acc);
        gemv_s<32>(slotp(G + 11), h3 + 512, hh, bg, acc);
        if (tid == 0) { lw(G + 12); lw(G + 13); }
        __syncthreads();
        if (tid == 0) { issue_one(G + 15); issue_one(G + 16); }

        // S7: Wih L3 (c12,c13) over new h2 + epi3
        gemv_s<32>(slotp(G + 12), h2,       hh, bg, acc);
        gemv_s<32>(slotp(G + 13), h2 + 512, hh, bg, acc);
        epi(3, acc);

        if (dec) {
            __syncthreads();   // h3 visible for projection
            if (isx) {
                float v = lb_s[ii];
#pragma unroll 8
                for (int h4 = 0; h4 < HID; h4++)
                    v += lw_s[h4 * INPUT + ii] * h3[h4 * 16 + bb];
                out[((size_t)(t - SEQ_LEN) * BATCH + b0 + bb) * INPUT + ii] = v;
                ind[ii * 16 + bb] = v;
            }
        }
        if (tid == 0) {
            lw(G + 14); lw(G + 15);           // next step's c0,c1
            if (t == SEQ_LEN - 1) wait_parity(rmb_u, 1);
        }
        __syncthreads();
        if (tid == 0) { issue_one(G + 17); issue_one(G + 18); }

        G += CPS;
    }
}

extern "C" void kernel_launch(void* const* d_in, const int* in_sizes, int n_in,
                              void* d_out, int out_size)
{
    const float* x    = (const float*)d_in[0];
    const float* eW0  = (const float*)d_in[1];
    const float* eWih = (const float*)d_in[2];
    const float* eWhh = (const float*)d_in[3];
    const float* eB   = (const float*)d_in[4];
    const float* dW0  = (const float*)d_in[5];
    const float* dWih = (const float*)d_in[6];
    const float* dWhh = (const float*)d_in[7];
    const float* dB   = (const float*)d_in[8];
    const float* linW = (const float*)d_in[9];
    const float* linB = (const float*)d_in[10];
    float* out = (float*)d_out;

    lstm36206574305735_pack<<<228, 256>>>(eW0, eWih, eWhh, dW0, dWih, dWhh);

    cudaFuncSetAttribute(lstm36206574305735_main,
                         cudaFuncAttributeMaxDynamicSharedMemorySize, SMEM_TOTAL_B);
    lstm36206574305735_main<<<NCTA, NTHR, SMEM_TOTAL_B>>>(x, eB, dB, linW, linB, out);
}